// round 15
// baseline (speedup 1.0000x reference)
#include <cuda_runtime.h>
#include <cuda_fp16.h>
#include <math.h>

#define N_NODES   50000
#define N_EDGES   800000
#define NUM_G     512
#define F         128
#define PADH      136        // smem row stride in halves (272B, 16B-aligned)
#define GEMM_BLOCKS ((N_NODES + 127) / 128)          // 391
#define FILL_BLOCKS ((N_EDGES + 255) / 256)          // 3125
#define GATHER_BLOCKS ((N_NODES * 32) / 256)         // 6250, exactly 50000 warps

// ---------------- device scratch (globals: allocation-free) ----------------
__device__ float  g_dinv[N_NODES];
__device__ int    g_deg[N_NODES];
__device__ int    g_start[N_NODES];
__device__ int    g_cur[N_NODES];
__device__ int    g_csr[N_EDGES];
__device__ int    g_total;
__device__ __half g_h16X[N_NODES * F];           // fp16 copy of input x
__device__ unsigned char g_f8A[N_NODES * F];     // hp (scaled X@W), e4m3
__device__ __half g_h16B[N_NODES * F];           // h1 (post-relu), fp16
__device__ __half g_w16a[F * F];                 // fp16 W1
__device__ __half g_w16b[F * F];                 // fp16 W2
__device__ float  g_pool[NUM_G * F];
__device__ float  g_cnt[NUM_G];
__device__ int    g_done;                        // gather2 completion counter

// ---------------- fp8 helpers ----------------------------------------------
__device__ __forceinline__ unsigned short e4m3pair(float lo, float hi) {
    unsigned short u;
    asm("cvt.rn.satfinite.e4m3x2.f32 %0, %1, %2;" : "=h"(u) : "f"(hi), "f"(lo));
    return u;
}
__device__ __forceinline__ float4 dec4(unsigned raw) {
    unsigned short lo = (unsigned short)(raw & 0xffffu);
    unsigned short hi = (unsigned short)(raw >> 16);
    unsigned h01, h23;
    asm("cvt.rn.f16x2.e4m3x2 %0, %1;" : "=r"(h01) : "h"(lo));
    asm("cvt.rn.f16x2.e4m3x2 %0, %1;" : "=r"(h23) : "h"(hi));
    float2 f01 = __half22float2(*(__half2*)&h01);
    float2 f23 = __half22float2(*(__half2*)&h23);
    return make_float4(f01.x, f01.y, f23.x, f23.y);
}

// ---------------- init: zero counters + convert W1/W2 to fp16 --------------
__global__ void k_init(const float* __restrict__ W1,
                       const float* __restrict__ W2) {
    int i = blockIdx.x * blockDim.x + threadIdx.x;
    if (i < N_NODES) g_deg[i] = 0;
    if (i < NUM_G * F) g_pool[i] = 0.0f;
    if (i < NUM_G) g_cnt[i] = 0.0f;
    if (i == 0) { g_total = 0; g_done = 0; }
    if (i < F * F) g_w16a[i] = __float2half_rn(W1[i]);
    else if (i < 2 * F * F) g_w16b[i - F * F] = __float2half_rn(W2[i - F * F]);
}

// ---------------- degree + graph-size histograms + x->fp16 convert ---------
__global__ void k_deg(const int* __restrict__ ei,
                      const int* __restrict__ batch,
                      const float* __restrict__ x) {
    int i = blockIdx.x * blockDim.x + threadIdx.x;
    if (i < N_EDGES) {
        atomicAdd(&g_deg[__ldg(&ei[N_EDGES + i])], 1);
        float4 v0 = __ldg((const float4*)&x[i * 8]);
        float4 v1 = __ldg((const float4*)&x[i * 8 + 4]);
        __half2 h0 = __float22half2_rn(make_float2(v0.x, v0.y));
        __half2 h1 = __float22half2_rn(make_float2(v0.z, v0.w));
        __half2 h2 = __float22half2_rn(make_float2(v1.x, v1.y));
        __half2 h3 = __float22half2_rn(make_float2(v1.z, v1.w));
        uint4 p;
        p.x = *(unsigned*)&h0; p.y = *(unsigned*)&h1;
        p.z = *(unsigned*)&h2; p.w = *(unsigned*)&h3;
        *(uint4*)&g_h16X[i * 8] = p;
    }
    if (i < N_NODES) atomicAdd(&g_cnt[__ldg(&batch[i])], 1.0f);
}

// ---------------- CSR offset alloc (warp-scan) + dinv = rsqrt(deg+1) --------
__global__ void k_alloc() {
    int i = blockIdx.x * blockDim.x + threadIdx.x;
    int lane = threadIdx.x & 31;
    int d = (i < N_NODES) ? g_deg[i] : 0;
    if (i < N_NODES) g_dinv[i] = rsqrtf((float)d + 1.0f);
    int xs = d;
#pragma unroll
    for (int o = 1; o < 32; o <<= 1) {
        int y = __shfl_up_sync(0xffffffff, xs, o);
        if (lane >= o) xs += y;
    }
    int warpsum = __shfl_sync(0xffffffff, xs, 31);
    int base = 0;
    if (lane == 31 && warpsum > 0) base = atomicAdd(&g_total, warpsum);
    base = __shfl_sync(0xffffffff, base, 31);
    int start = base + xs - d;
    if (i < N_NODES) { g_start[i] = start; g_cur[i] = start; }
}

// ---------------- tensor-core GEMM body: out8 = e4m3((X @ W) * dinv[row]) --
// 128x128x128 per CTA, 8 warps (4x2), mma.sync m16n8k16 f16->f32.
// R9/R10 original loop structure (measured fastest; do not "pipeline" it).
__device__ __forceinline__ void gemm_body(const __half* __restrict__ Xh,
                                          const __half* __restrict__ Wh,
                                          unsigned char* __restrict__ out8,
                                          int bid, __half* sm) {
    __half* Xs = sm;                  // [128][PADH]
    __half* Ws = sm + 128 * PADH;     // [128][PADH]

    int tid = threadIdx.x;
    int row0 = bid * 128;

#pragma unroll
    for (int c = tid; c < 2048; c += 256) {
        int r = c >> 4;
        int p = (c & 15) * 8;
        uint4 v = make_uint4(0u, 0u, 0u, 0u);
        int gr = row0 + r;
        if (gr < N_NODES) v = __ldg((const uint4*)&Xh[gr * F + p]);
        *(uint4*)&Xs[r * PADH + p] = v;
        uint4 w = __ldg((const uint4*)&Wh[r * F + p]);
        *(uint4*)&Ws[r * PADH + p] = w;
    }
    __syncthreads();

    int warp = tid >> 5, lane = tid & 31;
    int wm = (warp & 3) * 32;
    int wn = (warp >> 2) * 64;

    float acc[2][8][4];
#pragma unroll
    for (int mi = 0; mi < 2; mi++)
#pragma unroll
        for (int ni = 0; ni < 8; ni++)
#pragma unroll
            for (int k = 0; k < 4; k++) acc[mi][ni][k] = 0.0f;

    unsigned xbase = (unsigned)__cvta_generic_to_shared(Xs);
    unsigned wbase = (unsigned)__cvta_generic_to_shared(Ws);

#pragma unroll
    for (int k0 = 0; k0 < 128; k0 += 16) {
        unsigned a[2][4];
#pragma unroll
        for (int mi = 0; mi < 2; mi++) {
            int r = wm + mi * 16 + (lane & 15);
            int cp = k0 + (lane >> 4) * 8;
            unsigned addr = xbase + (unsigned)(r * PADH + cp) * 2u;
            asm volatile("ldmatrix.sync.aligned.m8n8.x4.shared.b16 {%0,%1,%2,%3}, [%4];"
                : "=r"(a[mi][0]), "=r"(a[mi][1]), "=r"(a[mi][2]), "=r"(a[mi][3])
                : "r"(addr));
        }
#pragma unroll
        for (int ni = 0; ni < 8; ni++) {
            int krow = k0 + (lane & 15);
            int col  = wn + ni * 8;
            unsigned addr = wbase + (unsigned)(krow * PADH + col) * 2u;
            unsigned b0, b1;
            asm volatile("ldmatrix.sync.aligned.m8n8.x2.trans.shared.b16 {%0,%1}, [%2];"
                : "=r"(b0), "=r"(b1) : "r"(addr));
#pragma unroll
            for (int mi = 0; mi < 2; mi++) {
                asm volatile("mma.sync.aligned.m16n8k16.row.col.f32.f16.f16.f32 "
                    "{%0,%1,%2,%3},{%4,%5,%6,%7},{%8,%9},{%0,%1,%2,%3};"
                    : "+f"(acc[mi][ni][0]), "+f"(acc[mi][ni][1]),
                      "+f"(acc[mi][ni][2]), "+f"(acc[mi][ni][3])
                    : "r"(a[mi][0]), "r"(a[mi][1]), "r"(a[mi][2]), "r"(a[mi][3]),
                      "r"(b0), "r"(b1));
            }
        }
    }

    int g  = lane >> 2;
    int tc = (lane & 3) * 2;
#pragma unroll
    for (int mi = 0; mi < 2; mi++) {
        int ra = row0 + wm + mi * 16 + g;
        int rb = ra + 8;
        float dva = (ra < N_NODES) ? g_dinv[ra] : 0.0f;
        float dvb = (rb < N_NODES) ? g_dinv[rb] : 0.0f;
#pragma unroll
        for (int ni = 0; ni < 8; ni++) {
            int col = wn + ni * 8 + tc;
            if (ra < N_NODES)
                *(unsigned short*)&out8[ra * F + col] =
                    e4m3pair(acc[mi][ni][0] * dva, acc[mi][ni][1] * dva);
            if (rb < N_NODES)
                *(unsigned short*)&out8[rb * F + col] =
                    e4m3pair(acc[mi][ni][2] * dvb, acc[mi][ni][3] * dvb);
        }
    }
}

// ---------------- fused: GEMM layer-1 (blocks 0..390) || CSR fill (rest) ----
__global__ __launch_bounds__(256) void k_gemm1_fill(const int* __restrict__ ei) {
    extern __shared__ __half sm[];
    if (blockIdx.x < GEMM_BLOCKS) {
        gemm_body(g_h16X, g_w16a, g_f8A, blockIdx.x, sm);
    } else {
        int e = (blockIdx.x - GEMM_BLOCKS) * 256 + threadIdx.x;
        if (e < N_EDGES) {
            int s = __ldg(&ei[e]);
            int d = __ldg(&ei[N_EDGES + e]);
            g_csr[atomicAdd(&g_cur[d], 1)] = s;
        }
    }
}

// ---------------- GEMM layer-2 ----------------------------------------------
__global__ __launch_bounds__(256) void k_gemm2() {
    extern __shared__ __half sm[];
    gemm_body(g_h16B, g_w16b, g_f8A, blockIdx.x, sm);
}

// ---------------- gather core: acc = hp[node] + sum_in hp[src] (fp32) -------
// R10 original: unroll 4 (measured faster than unroll 8).
__device__ __forceinline__ float4 gather_rows(const unsigned char* __restrict__ hp8,
                                              int node, int lane) {
    float4 acc = dec4(__ldg((const unsigned*)(hp8 + node * F + lane * 4)));  // self loop
    int start = g_start[node];
    int deg   = g_deg[node];
    for (int base = 0; base < deg; base += 32) {
        int rem = deg - base;
        int n = (rem < 32) ? rem : 32;
        int idx = (lane < n) ? __ldg(&g_csr[start + base + lane]) : 0;
#pragma unroll 4
        for (int j = 0; j < n; j++) {
            int s = __shfl_sync(0xffffffff, idx, j);
            float4 v = dec4(__ldg((const unsigned*)(hp8 + s * F + lane * 4)));
            acc.x += v.x; acc.y += v.y; acc.z += v.z; acc.w += v.w;
        }
    }
    return acc;
}

// ---------------- gather layer 1: h1 = relu(dinv*acc + b1) -> fp16 ---------
__global__ __launch_bounds__(256) void k_gather1(const float* __restrict__ bias) {
    int warp = (blockIdx.x * blockDim.x + threadIdx.x) >> 5;
    int lane = threadIdx.x & 31;
    int node = warp;            // exactly 50000 warps launched

    float4 acc = gather_rows(g_f8A, node, lane);
    float dv = g_dinv[node];
    float4 b4 = __ldg(&((const float4*)bias)[lane]);
    float4 r;
    r.x = fmaxf(acc.x * dv + b4.x, 0.0f);
    r.y = fmaxf(acc.y * dv + b4.y, 0.0f);
    r.z = fmaxf(acc.z * dv + b4.z, 0.0f);
    r.w = fmaxf(acc.w * dv + b4.w, 0.0f);

    __half2 o0 = __float22half2_rn(make_float2(r.x, r.y));
    __half2 o1 = __float22half2_rn(make_float2(r.z, r.w));
    uint2 p; p.x = *(unsigned*)&o0; p.y = *(unsigned*)&o1;
    *(uint2*)&g_h16B[node * F + lane * 4] = p;
}

// ---------------- gather layer 2 + pool + fused head ------------------------
__global__ __launch_bounds__(256) void k_gather2_final(const float* __restrict__ bias,
                                                       const int* __restrict__ batch,
                                                       const float* __restrict__ Wl,
                                                       const float* __restrict__ bl,
                                                       float* __restrict__ out) {
    int warp = (blockIdx.x * blockDim.x + threadIdx.x) >> 5;
    int lane = threadIdx.x & 31;
    int node = warp;            // exactly 50000 warps launched

    float4 acc = gather_rows(g_f8A, node, lane);
    float dv = g_dinv[node];
    float4 b4 = __ldg(&((const float4*)bias)[lane]);
    float4 r;
    r.x = fmaxf(acc.x * dv + b4.x, 0.0f);
    r.y = fmaxf(acc.y * dv + b4.y, 0.0f);
    r.z = fmaxf(acc.z * dv + b4.z, 0.0f);
    r.w = fmaxf(acc.w * dv + b4.w, 0.0f);

    int g = __ldg(&batch[node]);
    const float4* p = (const float4*)&g_pool[g * F + lane * 4];
    asm volatile("red.global.add.v4.f32 [%0], {%1, %2, %3, %4};"
                 :: "l"(p), "f"(r.x), "f"(r.y), "f"(r.z), "f"(r.w)
                 : "memory");

    // completion: last block computes the head
    __threadfence();
    __syncthreads();
    __shared__ int amLast;
    if (threadIdx.x == 0)
        amLast = (atomicAdd(&g_done, 1) == (int)gridDim.x - 1);
    __syncthreads();
    if (amLast) {
        __threadfence();
        __shared__ float Wls[F];
        if (threadIdx.x < F) Wls[threadIdx.x] = Wl[threadIdx.x];
        __syncthreads();
        float blv = bl[0];
        for (int gg = threadIdx.x; gg < NUM_G; gg += 256) {
            float sum = 0.0f;
#pragma unroll 8
            for (int k = 0; k < F; k++) sum += g_pool[gg * F + k] * Wls[k];
            float c = fmaxf(g_cnt[gg], 1.0f);
            float z = sum / c + blv;
            out[gg] = 1.0f / (1.0f + expf(-z));
        }
        if (threadIdx.x == 0) g_done = 0;   // reset for next replay
    }
}

// ---------------- launch ----------------------------------------------------
extern "C" void kernel_launch(void* const* d_in, const int* in_sizes, int n_in,
                              void* d_out, int out_size) {
    const float* x     = (const float*)d_in[0];
    const int*   ei    = (const int*)d_in[1];
    const int*   batch = (const int*)d_in[2];
    const float* W1    = (const float*)d_in[3];
    const float* b1    = (const float*)d_in[4];
    const float* W2    = (const float*)d_in[5];
    const float* b2    = (const float*)d_in[6];
    const float* Wl    = (const float*)d_in[7];
    const float* bl    = (const float*)d_in[8];
    float* out = (float*)d_out;

    const int smem_bytes = 2 * 128 * PADH * sizeof(__half);   // 69632
    cudaFuncSetAttribute(k_gemm1_fill,
                         cudaFuncAttributeMaxDynamicSharedMemorySize, smem_bytes);
    cudaFuncSetAttribute(k_gemm2,
                         cudaFuncAttributeMaxDynamicSharedMemorySize, smem_bytes);

    k_init<<<(NUM_G * F + 255) / 256, 256>>>(W1, W2);
    k_deg<<<(N_EDGES + 255) / 256, 256>>>(ei, batch, x);
    k_alloc<<<(N_NODES + 255) / 256, 256>>>();

    // layer 1: GEMM (x16 -> hp1 fp8) overlapped with CSR fill (R10 pattern)
    k_gemm1_fill<<<GEMM_BLOCKS + FILL_BLOCKS, 256, smem_bytes>>>(ei);
    k_gather1<<<GATHER_BLOCKS, 256>>>(b1);

    // layer 2: h1 (fp16) -> hp2 (fp8) -> pool -> head (fused)
    k_gemm2<<<GEMM_BLOCKS, 256, smem_bytes>>>();
    k_gather2_final<<<GATHER_BLOCKS, 256>>>(b2, batch, Wl, bl, out);
}

// round 16
// speedup vs baseline: 1.7495x; 1.7495x over previous
#include <cuda_runtime.h>
#include <cuda_fp16.h>
#include <math.h>

#define N_NODES   50000
#define N_EDGES   800000
#define NUM_G     512
#define F         128
#define PADH      136        // smem row stride in halves (272B, 16B-aligned)
#define GEMM_BLOCKS ((N_NODES + 127) / 128)          // 391
#define FILL_BLOCKS ((N_EDGES + 255) / 256)          // 3125
#define GATHER_BLOCKS ((N_NODES * 32) / 256)         // 6250, exactly 50000 warps

// ---------------- device scratch (globals: allocation-free) ----------------
__device__ float  g_dinv[N_NODES];
__device__ int    g_deg[N_NODES];
__device__ int    g_start[N_NODES];
__device__ int    g_cur[N_NODES];
__device__ int    g_csr[N_EDGES];
__device__ int    g_total;
__device__ unsigned char g_f8A[N_NODES * F];     // hp (scaled X@W), e4m3
__device__ __half g_h16B[N_NODES * F];           // h1 (post-relu), fp16
__device__ __half g_w16a[F * F];                 // fp16 W1
__device__ __half g_w16b[F * F];                 // fp16 W2
__device__ float  g_pool[NUM_G * F];
__device__ float  g_cnt[NUM_G];

// ---------------- fp8 helpers ----------------------------------------------
__device__ __forceinline__ unsigned short e4m3pair(float lo, float hi) {
    unsigned short u;
    asm("cvt.rn.satfinite.e4m3x2.f32 %0, %1, %2;" : "=h"(u) : "f"(hi), "f"(lo));
    return u;
}
__device__ __forceinline__ float4 dec4(unsigned raw) {
    unsigned short lo = (unsigned short)(raw & 0xffffu);
    unsigned short hi = (unsigned short)(raw >> 16);
    unsigned h01, h23;
    asm("cvt.rn.f16x2.e4m3x2 %0, %1;" : "=r"(h01) : "h"(lo));
    asm("cvt.rn.f16x2.e4m3x2 %0, %1;" : "=r"(h23) : "h"(hi));
    float2 f01 = __half22float2(*(__half2*)&h01);
    float2 f23 = __half22float2(*(__half2*)&h23);
    return make_float4(f01.x, f01.y, f23.x, f23.y);
}

// ---------------- init: zero counters + convert W1/W2 to fp16 --------------
__global__ void k_init(const float* __restrict__ W1,
                       const float* __restrict__ W2) {
    int i = blockIdx.x * blockDim.x + threadIdx.x;
    if (i < N_NODES) g_deg[i] = 0;
    if (i < NUM_G * F) g_pool[i] = 0.0f;
    if (i < NUM_G) g_cnt[i] = 0.0f;
    if (i == 0) g_total = 0;
    if (i < F * F) g_w16a[i] = __float2half_rn(W1[i]);
    else if (i < 2 * F * F) g_w16b[i - F * F] = __float2half_rn(W2[i - F * F]);
}

// ---------------- degree + graph-size histograms (x-convert removed) --------
__global__ void k_deg(const int* __restrict__ ei,
                      const int* __restrict__ batch) {
    int i = blockIdx.x * blockDim.x + threadIdx.x;
    if (i < N_EDGES) atomicAdd(&g_deg[__ldg(&ei[N_EDGES + i])], 1);
    if (i < N_NODES) atomicAdd(&g_cnt[__ldg(&batch[i])], 1.0f);
}

// ---------------- CSR offset alloc (warp-scan) + dinv = rsqrt(deg+1) --------
__global__ void k_alloc() {
    int i = blockIdx.x * blockDim.x + threadIdx.x;
    int lane = threadIdx.x & 31;
    int d = (i < N_NODES) ? g_deg[i] : 0;
    if (i < N_NODES) g_dinv[i] = rsqrtf((float)d + 1.0f);
    int xs = d;
#pragma unroll
    for (int o = 1; o < 32; o <<= 1) {
        int y = __shfl_up_sync(0xffffffff, xs, o);
        if (lane >= o) xs += y;
    }
    int warpsum = __shfl_sync(0xffffffff, xs, 31);
    int base = 0;
    if (lane == 31 && warpsum > 0) base = atomicAdd(&g_total, warpsum);
    base = __shfl_sync(0xffffffff, base, 31);
    int start = base + xs - d;
    if (i < N_NODES) { g_start[i] = start; g_cur[i] = start; }
}

// ---------------- tensor-core GEMM body: out8 = e4m3((X @ W) * dinv[row]) --
// 128x128x128 per CTA, 8 warps (4x2), mma.sync m16n8k16 f16->f32.
// R9/R10 original loop structure (measured fastest; do not "pipeline" it).
// XF32: stage fp32 input with in-register fp16 conversion (layer 1).
template <bool XF32>
__device__ __forceinline__ void gemm_body(const void* __restrict__ Xv,
                                          const __half* __restrict__ Wh,
                                          unsigned char* __restrict__ out8,
                                          int bid, __half* sm) {
    __half* Xs = sm;                  // [128][PADH]
    __half* Ws = sm + 128 * PADH;     // [128][PADH]

    int tid = threadIdx.x;
    int row0 = bid * 128;

#pragma unroll
    for (int c = tid; c < 2048; c += 256) {
        int r = c >> 4;
        int p = (c & 15) * 8;
        int gr = row0 + r;
        uint4 v = make_uint4(0u, 0u, 0u, 0u);
        if (gr < N_NODES) {
            if (XF32) {
                const float* X = (const float*)Xv;
                float4 f0 = __ldg((const float4*)&X[gr * F + p]);
                float4 f1 = __ldg((const float4*)&X[gr * F + p + 4]);
                __half2 h0 = __float22half2_rn(make_float2(f0.x, f0.y));
                __half2 h1 = __float22half2_rn(make_float2(f0.z, f0.w));
                __half2 h2 = __float22half2_rn(make_float2(f1.x, f1.y));
                __half2 h3 = __float22half2_rn(make_float2(f1.z, f1.w));
                v.x = *(unsigned*)&h0; v.y = *(unsigned*)&h1;
                v.z = *(unsigned*)&h2; v.w = *(unsigned*)&h3;
            } else {
                v = __ldg((const uint4*)&((const __half*)Xv)[gr * F + p]);
            }
        }
        *(uint4*)&Xs[r * PADH + p] = v;
        uint4 w = __ldg((const uint4*)&Wh[r * F + p]);
        *(uint4*)&Ws[r * PADH + p] = w;
    }
    __syncthreads();

    int warp = tid >> 5, lane = tid & 31;
    int wm = (warp & 3) * 32;
    int wn = (warp >> 2) * 64;

    float acc[2][8][4];
#pragma unroll
    for (int mi = 0; mi < 2; mi++)
#pragma unroll
        for (int ni = 0; ni < 8; ni++)
#pragma unroll
            for (int k = 0; k < 4; k++) acc[mi][ni][k] = 0.0f;

    unsigned xbase = (unsigned)__cvta_generic_to_shared(Xs);
    unsigned wbase = (unsigned)__cvta_generic_to_shared(Ws);

#pragma unroll
    for (int k0 = 0; k0 < 128; k0 += 16) {
        unsigned a[2][4];
#pragma unroll
        for (int mi = 0; mi < 2; mi++) {
            int r = wm + mi * 16 + (lane & 15);
            int cp = k0 + (lane >> 4) * 8;
            unsigned addr = xbase + (unsigned)(r * PADH + cp) * 2u;
            asm volatile("ldmatrix.sync.aligned.m8n8.x4.shared.b16 {%0,%1,%2,%3}, [%4];"
                : "=r"(a[mi][0]), "=r"(a[mi][1]), "=r"(a[mi][2]), "=r"(a[mi][3])
                : "r"(addr));
        }
#pragma unroll
        for (int ni = 0; ni < 8; ni++) {
            int krow = k0 + (lane & 15);
            int col  = wn + ni * 8;
            unsigned addr = wbase + (unsigned)(krow * PADH + col) * 2u;
            unsigned b0, b1;
            asm volatile("ldmatrix.sync.aligned.m8n8.x2.trans.shared.b16 {%0,%1}, [%2];"
                : "=r"(b0), "=r"(b1) : "r"(addr));
#pragma unroll
            for (int mi = 0; mi < 2; mi++) {
                asm volatile("mma.sync.aligned.m16n8k16.row.col.f32.f16.f16.f32 "
                    "{%0,%1,%2,%3},{%4,%5,%6,%7},{%8,%9},{%0,%1,%2,%3};"
                    : "+f"(acc[mi][ni][0]), "+f"(acc[mi][ni][1]),
                      "+f"(acc[mi][ni][2]), "+f"(acc[mi][ni][3])
                    : "r"(a[mi][0]), "r"(a[mi][1]), "r"(a[mi][2]), "r"(a[mi][3]),
                      "r"(b0), "r"(b1));
            }
        }
    }

    int g  = lane >> 2;
    int tc = (lane & 3) * 2;
#pragma unroll
    for (int mi = 0; mi < 2; mi++) {
        int ra = row0 + wm + mi * 16 + g;
        int rb = ra + 8;
        float dva = (ra < N_NODES) ? g_dinv[ra] : 0.0f;
        float dvb = (rb < N_NODES) ? g_dinv[rb] : 0.0f;
#pragma unroll
        for (int ni = 0; ni < 8; ni++) {
            int col = wn + ni * 8 + tc;
            if (ra < N_NODES)
                *(unsigned short*)&out8[ra * F + col] =
                    e4m3pair(acc[mi][ni][0] * dva, acc[mi][ni][1] * dva);
            if (rb < N_NODES)
                *(unsigned short*)&out8[rb * F + col] =
                    e4m3pair(acc[mi][ni][2] * dvb, acc[mi][ni][3] * dvb);
        }
    }
}

// ---------------- fused: GEMM layer-1 (blocks 0..390) || CSR fill (rest) ----
__global__ __launch_bounds__(256) void k_gemm1_fill(const int* __restrict__ ei,
                                                    const float* __restrict__ x) {
    extern __shared__ __half sm[];
    if (blockIdx.x < GEMM_BLOCKS) {
        gemm_body<true>(x, g_w16a, g_f8A, blockIdx.x, sm);
    } else {
        int e = (blockIdx.x - GEMM_BLOCKS) * 256 + threadIdx.x;
        if (e < N_EDGES) {
            int s = __ldg(&ei[e]);
            int d = __ldg(&ei[N_EDGES + e]);
            g_csr[atomicAdd(&g_cur[d], 1)] = s;
        }
    }
}

// ---------------- GEMM layer-2 ----------------------------------------------
__global__ __launch_bounds__(256) void k_gemm2() {
    extern __shared__ __half sm[];
    gemm_body<false>(g_h16B, g_w16b, g_f8A, blockIdx.x, sm);
}

// ---------------- gather core: acc = hp[node] + sum_in hp[src] (fp32) -------
__device__ __forceinline__ float4 gather_rows(const unsigned char* __restrict__ hp8,
                                              int node, int lane) {
    float4 acc = dec4(__ldg((const unsigned*)(hp8 + node * F + lane * 4)));  // self loop
    int start = g_start[node];
    int deg   = g_deg[node];
    for (int base = 0; base < deg; base += 32) {
        int rem = deg - base;
        int n = (rem < 32) ? rem : 32;
        int idx = (lane < n) ? __ldg(&g_csr[start + base + lane]) : 0;
#pragma unroll 4
        for (int j = 0; j < n; j++) {
            int s = __shfl_sync(0xffffffff, idx, j);
            float4 v = dec4(__ldg((const unsigned*)(hp8 + s * F + lane * 4)));
            acc.x += v.x; acc.y += v.y; acc.z += v.z; acc.w += v.w;
        }
    }
    return acc;
}

// ---------------- gather layer 1: h1 = relu(dinv*acc + b1) -> fp16 ---------
__global__ __launch_bounds__(256) void k_gather1(const float* __restrict__ bias) {
    int warp = (blockIdx.x * blockDim.x + threadIdx.x) >> 5;
    int lane = threadIdx.x & 31;
    int node = warp;            // exactly 50000 warps launched

    float4 acc = gather_rows(g_f8A, node, lane);
    float dv = g_dinv[node];
    float4 b4 = __ldg(&((const float4*)bias)[lane]);
    float4 r;
    r.x = fmaxf(acc.x * dv + b4.x, 0.0f);
    r.y = fmaxf(acc.y * dv + b4.y, 0.0f);
    r.z = fmaxf(acc.z * dv + b4.z, 0.0f);
    r.w = fmaxf(acc.w * dv + b4.w, 0.0f);

    __half2 o0 = __float22half2_rn(make_float2(r.x, r.y));
    __half2 o1 = __float22half2_rn(make_float2(r.z, r.w));
    uint2 p; p.x = *(unsigned*)&o0; p.y = *(unsigned*)&o1;
    *(uint2*)&g_h16B[node * F + lane * 4] = p;
}

// ---------------- gather layer 2 + pool ------------------------------------
__global__ __launch_bounds__(256) void k_gather2(const float* __restrict__ bias,
                                                 const int* __restrict__ batch) {
    int warp = (blockIdx.x * blockDim.x + threadIdx.x) >> 5;
    int lane = threadIdx.x & 31;
    int node = warp;            // exactly 50000 warps launched

    float4 acc = gather_rows(g_f8A, node, lane);
    float dv = g_dinv[node];
    float4 b4 = __ldg(&((const float4*)bias)[lane]);
    float4 r;
    r.x = fmaxf(acc.x * dv + b4.x, 0.0f);
    r.y = fmaxf(acc.y * dv + b4.y, 0.0f);
    r.z = fmaxf(acc.z * dv + b4.z, 0.0f);
    r.w = fmaxf(acc.w * dv + b4.w, 0.0f);

    int g = __ldg(&batch[node]);
    const float4* p = (const float4*)&g_pool[g * F + lane * 4];
    asm volatile("red.global.add.v4.f32 [%0], {%1, %2, %3, %4};"
                 :: "l"(p), "f"(r.x), "f"(r.y), "f"(r.z), "f"(r.w)
                 : "memory");
}

// ---------------- head: out[g] = sigmoid(dot(pool[g]/cnt, Wl) + bl) --------
__global__ void k_final(const float* __restrict__ Wl,
                        const float* __restrict__ bl,
                        float* __restrict__ out) {
    __shared__ float Wls[F];
    int tid = threadIdx.x;
    if (tid < F) Wls[tid] = Wl[tid];
    __syncthreads();

    int g = blockIdx.x * blockDim.x + tid;
    if (g < NUM_G) {
        float sum = 0.0f;
#pragma unroll 8
        for (int k = 0; k < F; k++) sum += g_pool[g * F + k] * Wls[k];
        float c = fmaxf(g_cnt[g], 1.0f);
        float z = sum / c + bl[0];
        out[g] = 1.0f / (1.0f + expf(-z));
    }
}

// ---------------- launch ----------------------------------------------------
extern "C" void kernel_launch(void* const* d_in, const int* in_sizes, int n_in,
                              void* d_out, int out_size) {
    const float* x     = (const float*)d_in[0];
    const int*   ei    = (const int*)d_in[1];
    const int*   batch = (const int*)d_in[2];
    const float* W1    = (const float*)d_in[3];
    const float* b1    = (const float*)d_in[4];
    const float* W2    = (const float*)d_in[5];
    const float* b2    = (const float*)d_in[6];
    const float* Wl    = (const float*)d_in[7];
    const float* bl    = (const float*)d_in[8];
    float* out = (float*)d_out;

    const int smem_bytes = 2 * 128 * PADH * sizeof(__half);   // 69632
    cudaFuncSetAttribute(k_gemm1_fill,
                         cudaFuncAttributeMaxDynamicSharedMemorySize, smem_bytes);
    cudaFuncSetAttribute(k_gemm2,
                         cudaFuncAttributeMaxDynamicSharedMemorySize, smem_bytes);

    k_init<<<(NUM_G * F + 255) / 256, 256>>>(W1, W2);
    k_deg<<<(N_EDGES + 255) / 256, 256>>>(ei, batch);
    k_alloc<<<(N_NODES + 255) / 256, 256>>>();

    // layer 1: GEMM (x fp32 -> hp1 fp8, converting in-kernel) || CSR fill
    k_gemm1_fill<<<GEMM_BLOCKS + FILL_BLOCKS, 256, smem_bytes>>>(ei, x);
    k_gather1<<<GATHER_BLOCKS, 256>>>(b1);

    // layer 2: h1 (fp16) -> hp2 (fp8) -> pool
    k_gemm2<<<GEMM_BLOCKS, 256, smem_bytes>>>();
    k_gather2<<<GATHER_BLOCKS, 256>>>(b2, batch);

    k_final<<<(NUM_G + 255) / 256, 256>>>(Wl, bl, out);
}